// round 2
// baseline (speedup 1.0000x reference)
#include <cuda_runtime.h>

#define NEGV (-1e10f)

constexpr int Bb = 2;
constexpr int Hh = 16;
constexpr int Ss = 2048;
constexpr int Dh = 128;
constexpr int Dm = 2048;     // Hh*Dh
constexpr int NT = 16;       // Ss / 128 tiles
constexpr int TOPK = 8;

// Scratch (static device globals; no dynamic allocation allowed)
__device__ float g_q[Bb * Hh * Ss * Dh];    // [b,h,s,d]
__device__ float g_k[Bb * Hh * Ss * Dh];
__device__ float g_v[Bb * Hh * Ss * Dh];
__device__ float g_ao[Bb * Ss * Dm];        // attention out, [b,s,h*d]

// ---------------------------------------------------------------------------
// Double-buffered 128x128x16 fp32 GEMM core. 256 threads, 8x8 per thread.
// A is [4096 x 2048] row-major, B is [2048 x (ncols)] row-major slice at n0.
// ---------------------------------------------------------------------------
struct GemmAcc { float a[8][8]; };

__device__ __forceinline__ void gemm_core_db(
    const float* __restrict__ A, const float* __restrict__ Bm,
    int m0, int n0, float acc[8][8],
    float (*As)[16][128], float (*Bs)[16][128])
{
    const int tid = threadIdx.x;
    const int ty = tid >> 4, tx = tid & 15;

    // per-thread load coordinates (2 float4 each for A and B)
    const int arow0 = tid >> 2;                // 0..63
    const int akc0  = (tid & 3) << 2;          // 0,4,8,12
    const int brow0 = tid >> 5;                // 0..7
    const int bcc0  = (tid & 31) << 2;         // 0..124

    // prologue: load tile 0 into buffer 0
    {
        float4 va0 = *(const float4*)(A + (size_t)(m0 + arow0) * 2048 + akc0);
        float4 va1 = *(const float4*)(A + (size_t)(m0 + arow0 + 64) * 2048 + akc0);
        float4 vb0 = *(const float4*)(Bm + (size_t)brow0 * 2048 + n0 + bcc0);
        float4 vb1 = *(const float4*)(Bm + (size_t)(brow0 + 8) * 2048 + n0 + bcc0);
        As[0][akc0 + 0][arow0] = va0.x; As[0][akc0 + 1][arow0] = va0.y;
        As[0][akc0 + 2][arow0] = va0.z; As[0][akc0 + 3][arow0] = va0.w;
        As[0][akc0 + 0][arow0 + 64] = va1.x; As[0][akc0 + 1][arow0 + 64] = va1.y;
        As[0][akc0 + 2][arow0 + 64] = va1.z; As[0][akc0 + 3][arow0 + 64] = va1.w;
        *(float4*)&Bs[0][brow0][bcc0] = vb0;
        *(float4*)&Bs[0][brow0 + 8][bcc0] = vb1;
    }
    __syncthreads();

    int cur = 0;
    for (int k0 = 0; k0 < 2048; k0 += 16) {
        float4 va0, va1, vb0, vb1;
        const bool more = (k0 + 16) < 2048;
        if (more) {
            int kn = k0 + 16;
            va0 = *(const float4*)(A + (size_t)(m0 + arow0) * 2048 + kn + akc0);
            va1 = *(const float4*)(A + (size_t)(m0 + arow0 + 64) * 2048 + kn + akc0);
            vb0 = *(const float4*)(Bm + (size_t)(kn + brow0) * 2048 + n0 + bcc0);
            vb1 = *(const float4*)(Bm + (size_t)(kn + brow0 + 8) * 2048 + n0 + bcc0);
        }
#pragma unroll
        for (int kc = 0; kc < 16; ++kc) {
            float a[8], b[8];
            *(float4*)&a[0] = *(const float4*)&As[cur][kc][ty * 8];
            *(float4*)&a[4] = *(const float4*)&As[cur][kc][ty * 8 + 4];
            *(float4*)&b[0] = *(const float4*)&Bs[cur][kc][tx * 8];
            *(float4*)&b[4] = *(const float4*)&Bs[cur][kc][tx * 8 + 4];
#pragma unroll
            for (int i = 0; i < 8; i++)
#pragma unroll
                for (int j = 0; j < 8; j++) acc[i][j] += a[i] * b[j];
        }
        if (more) {
            int nxt = cur ^ 1;
            As[nxt][akc0 + 0][arow0] = va0.x; As[nxt][akc0 + 1][arow0] = va0.y;
            As[nxt][akc0 + 2][arow0] = va0.z; As[nxt][akc0 + 3][arow0] = va0.w;
            As[nxt][akc0 + 0][arow0 + 64] = va1.x; As[nxt][akc0 + 1][arow0 + 64] = va1.y;
            As[nxt][akc0 + 2][arow0 + 64] = va1.z; As[nxt][akc0 + 3][arow0 + 64] = va1.w;
            *(float4*)&Bs[nxt][brow0][bcc0] = vb0;
            *(float4*)&Bs[nxt][brow0 + 8][bcc0] = vb1;
            __syncthreads();
            cur = nxt;
        }
    }
}

// ---------------------------------------------------------------------------
// QKV projection GEMM: C = x @ W for W in {wq,wk,wv}
// grid = (32, 48): y>>4 selects weight, y&15 selects 128-wide N tile (== head)
// Epilogue scatters into [b,h,s,d] layout.
// ---------------------------------------------------------------------------
__global__ __launch_bounds__(256, 2) void qkv_gemm(
    const float* __restrict__ x,
    const float* __restrict__ wq,
    const float* __restrict__ wk,
    const float* __restrict__ wv)
{
    __shared__ float As[2][16][128];
    __shared__ float Bs[2][16][128];

    const int tid = threadIdx.x;
    const int ty = tid >> 4, tx = tid & 15;
    const int which = blockIdx.y >> 4;
    const int n0 = (blockIdx.y & 15) * 128;
    const int m0 = blockIdx.x * 128;
    const float* Bm = (which == 0) ? wq : (which == 1) ? wk : wv;

    float acc[8][8];
#pragma unroll
    for (int i = 0; i < 8; i++)
#pragma unroll
        for (int j = 0; j < 8; j++) acc[i][j] = 0.f;

    gemm_core_db(x, Bm, m0, n0, acc, As, Bs);

    float* dst = (which == 0) ? g_q : (which == 1) ? g_k : g_v;
    const int h = n0 >> 7;
#pragma unroll
    for (int i = 0; i < 8; i++) {
        int m = m0 + ty * 8 + i;
        int b = m >> 11, s = m & 2047;
        float* p = dst + (((size_t)(b * Hh + h) * Ss + s) * Dh) + tx * 8;
        *(float4*)p = make_float4(acc[i][0], acc[i][1], acc[i][2], acc[i][3]);
        *(float4*)(p + 4) = make_float4(acc[i][4], acc[i][5], acc[i][6], acc[i][7]);
    }
}

// ---------------------------------------------------------------------------
// Output projection GEMM: out = g_ao @ wo
// ---------------------------------------------------------------------------
__global__ __launch_bounds__(256, 2) void oproj_gemm(
    const float* __restrict__ wo, float* __restrict__ out)
{
    __shared__ float As[2][16][128];
    __shared__ float Bs[2][16][128];

    const int tid = threadIdx.x;
    const int ty = tid >> 4, tx = tid & 15;
    const int n0 = blockIdx.y * 128;
    const int m0 = blockIdx.x * 128;

    float acc[8][8];
#pragma unroll
    for (int i = 0; i < 8; i++)
#pragma unroll
        for (int j = 0; j < 8; j++) acc[i][j] = 0.f;

    gemm_core_db(g_ao, wo, m0, n0, acc, As, Bs);

#pragma unroll
    for (int i = 0; i < 8; i++) {
        int m = m0 + ty * 8 + i;
        float* p = out + (size_t)m * 2048 + n0 + tx * 8;
        *(float4*)p = make_float4(acc[i][0], acc[i][1], acc[i][2], acc[i][3]);
        *(float4*)(p + 4) = make_float4(acc[i][4], acc[i][5], acc[i][6], acc[i][7]);
    }
}

// ---------------------------------------------------------------------------
// RoPE (rotate_half form), in-place on g_q and g_k.
// ---------------------------------------------------------------------------
__global__ void rope_kernel(const float* __restrict__ cosr,
                            const float* __restrict__ sinr)
{
    int idx = blockIdx.x * 256 + threadIdx.x;
    if (idx >= Bb * Hh * Ss * 64) return;
    int d = idx & 63;
    int s = (idx >> 6) & (Ss - 1);
    int bh = idx >> 17;
    float c = cosr[s * 64 + d];
    float sn = sinr[s * 64 + d];
    size_t base = (size_t)bh * Ss * Dh + (size_t)s * Dh;
    float q0 = g_q[base + d], q1 = g_q[base + d + 64];
    g_q[base + d] = q0 * c - q1 * sn;
    g_q[base + d + 64] = q1 * c + q0 * sn;
    float k0 = g_k[base + d], k1 = g_k[base + d + 64];
    g_k[base + d] = k0 * c - k1 * sn;
    g_k[base + d + 64] = k1 * c + k0 * sn;
}

// ---------------------------------------------------------------------------
// Flash-style causal attention. grid = (B*H, S/128). 256 threads.
// Q/K tiles stored d-major (transposed) in SMEM, stride 132.
// Online softmax; P staged through SMEM for the PV GEMM.
// ---------------------------------------------------------------------------
__global__ __launch_bounds__(256, 1) void flash_kernel()
{
    extern __shared__ float sm[];
    float* Qt = sm;                       // [128 d][132]
    float* Kt = sm + 128 * 132;           // [128 d][132]
    float* Ps = sm + 2 * 128 * 132;       // [128 row][132]
    float* Vs = sm + 3 * 128 * 132;       // [16 kk][128 d]

    const int bh = blockIdx.x;
    const int qt = blockIdx.y;
    const int tid = threadIdx.x;
    const int ty = tid >> 4, tx = tid & 15;
    const float scale = 0.08838834764831845f;   // 1/sqrt(128)

    const float* Qg = g_q + ((size_t)bh * Ss + (size_t)qt * 128) * Dh;
    const float* Kg = g_k + (size_t)bh * Ss * Dh;
    const float* Vg = g_v + (size_t)bh * Ss * Dh;

    // Load + transpose Q tile
#pragma unroll
    for (int it = 0; it < 16; ++it) {
        int idx = it * 256 + tid;
        int row = idx >> 5;
        int c4 = (idx & 31) << 2;
        float4 v = *(const float4*)(Qg + (size_t)row * Dh + c4);
        Qt[(c4 + 0) * 132 + row] = v.x;
        Qt[(c4 + 1) * 132 + row] = v.y;
        Qt[(c4 + 2) * 132 + row] = v.z;
        Qt[(c4 + 3) * 132 + row] = v.w;
    }

    float o[8][8];
    float mrow[8], lrow[8];
#pragma unroll
    for (int i = 0; i < 8; i++) {
        mrow[i] = -1e30f; lrow[i] = 0.f;
#pragma unroll
        for (int j = 0; j < 8; j++) o[i][j] = 0.f;
    }
    __syncthreads();   // Qt visible

    for (int kt = 0; kt <= qt; ++kt) {
        // Load + transpose K tile
#pragma unroll
        for (int it = 0; it < 16; ++it) {
            int idx = it * 256 + tid;
            int row = idx >> 5;
            int c4 = (idx & 31) << 2;
            float4 v = *(const float4*)(Kg + (size_t)(kt * 128 + row) * Dh + c4);
            Kt[(c4 + 0) * 132 + row] = v.x;
            Kt[(c4 + 1) * 132 + row] = v.y;
            Kt[(c4 + 2) * 132 + row] = v.z;
            Kt[(c4 + 3) * 132 + row] = v.w;
        }
        __syncthreads();

        // S = Q K^T (8x8 per thread)
        float sacc[8][8];
#pragma unroll
        for (int i = 0; i < 8; i++)
#pragma unroll
            for (int j = 0; j < 8; j++) sacc[i][j] = 0.f;

#pragma unroll 4
        for (int d = 0; d < Dh; ++d) {
            float a[8], b[8];
            *(float4*)&a[0] = *(const float4*)&Qt[d * 132 + ty * 8];
            *(float4*)&a[4] = *(const float4*)&Qt[d * 132 + ty * 8 + 4];
            *(float4*)&b[0] = *(const float4*)&Kt[d * 132 + tx * 8];
            *(float4*)&b[4] = *(const float4*)&Kt[d * 132 + tx * 8 + 4];
#pragma unroll
            for (int i = 0; i < 8; i++)
#pragma unroll
                for (int j = 0; j < 8; j++) sacc[i][j] += a[i] * b[j];
        }

        // scale + causal mask (only diag tile needs masking)
        const bool diag = (kt == qt);
        const int rb = ty * 8, cb = tx * 8;
#pragma unroll
        for (int i = 0; i < 8; i++)
#pragma unroll
            for (int j = 0; j < 8; j++) {
                float v = sacc[i][j] * scale;
                if (diag && (cb + j > rb + i)) v = NEGV;
                sacc[i][j] = v;
            }

        // online softmax update (row reductions across the 16 tx lanes)
#pragma unroll
        for (int i = 0; i < 8; i++) {
            float tm = sacc[i][0];
#pragma unroll
            for (int j = 1; j < 8; j++) tm = fmaxf(tm, sacc[i][j]);
#pragma unroll
            for (int off = 8; off; off >>= 1)
                tm = fmaxf(tm, __shfl_xor_sync(0xffffffffu, tm, off));
            float mn = fmaxf(mrow[i], tm);
            float al = __expf(mrow[i] - mn);
            mrow[i] = mn;
            float rs = 0.f;
#pragma unroll
            for (int j = 0; j < 8; j++) {
                float p = __expf(sacc[i][j] - mn);
                sacc[i][j] = p;
                rs += p;
            }
#pragma unroll
            for (int off = 8; off; off >>= 1)
                rs += __shfl_xor_sync(0xffffffffu, rs, off);
            lrow[i] = lrow[i] * al + rs;
#pragma unroll
            for (int j = 0; j < 8; j++) o[i][j] *= al;
        }

        // stage P into SMEM
#pragma unroll
        for (int i = 0; i < 8; i++) {
            float* pp = &Ps[(ty * 8 + i) * 132 + tx * 8];
            *(float4*)pp = make_float4(sacc[i][0], sacc[i][1], sacc[i][2], sacc[i][3]);
            *(float4*)(pp + 4) = make_float4(sacc[i][4], sacc[i][5], sacc[i][6], sacc[i][7]);
        }
        __syncthreads();

        // O += P @ V, streaming V rows in chunks of 16
        const float* Vt = Vg + (size_t)kt * 128 * Dh;
        for (int kk0 = 0; kk0 < 128; kk0 += 16) {
#pragma unroll
            for (int it = 0; it < 2; ++it) {
                int idx = it * 256 + tid;
                int r = idx >> 5;
                int c4 = (idx & 31) << 2;
                *(float4*)&Vs[r * 128 + c4] =
                    *(const float4*)(Vt + (size_t)(kk0 + r) * Dh + c4);
            }
            __syncthreads();
#pragma unroll
            for (int kq = 0; kq < 4; ++kq) {
                float4 p4[8];
#pragma unroll
                for (int i = 0; i < 8; i++)
                    p4[i] = *(const float4*)&Ps[(ty * 8 + i) * 132 + kk0 + kq * 4];
#pragma unroll
                for (int c = 0; c < 4; c++) {
                    float b[8];
                    *(float4*)&b[0] = *(const float4*)&Vs[(kq * 4 + c) * 128 + tx * 8];
                    *(float4*)&b[4] = *(const float4*)&Vs[(kq * 4 + c) * 128 + tx * 8 + 4];
#pragma unroll
                    for (int i = 0; i < 8; i++) {
                        float pv = (&p4[i].x)[c];
#pragma unroll
                        for (int j = 0; j < 8; j++) o[i][j] += pv * b[j];
                    }
                }
            }
            __syncthreads();
        }
    }

    // normalize + write to [b, s, h*128+d]
    const int b = bh >> 4, h = bh & 15;
#pragma unroll
    for (int i = 0; i < 8; i++) {
        int s = qt * 128 + ty * 8 + i;
        float inv = 1.0f / lrow[i];
        float* p = g_ao + ((size_t)(b * Ss + s)) * Dm + h * 128 + tx * 8;
        *(float4*)p = make_float4(o[i][0] * inv, o[i][1] * inv, o[i][2] * inv, o[i][3] * inv);
        *(float4*)(p + 4) = make_float4(o[i][4] * inv, o[i][5] * inv, o[i][6] * inv, o[i][7] * inv);
    }
}

// ---------------------------------------------------------------------------
// Tile scoring + top-k. One block per (b,h). Matches reference math:
// softmax weights of the last query row of each tile, per-tile max, stable
// top-8 (ties -> lowest index, matching jax.lax.top_k). Normalization is
// rank-invariant and skipped; masked weights underflow to exactly 0 in both.
// ---------------------------------------------------------------------------
__global__ __launch_bounds__(256) void score_kernel(float* __restrict__ out_idx)
{
    __shared__ float qrow[128];
    __shared__ float red[256];
    __shared__ float ts[NT];

    const int bh = blockIdx.x;
    const int tid = threadIdx.x;
    const float scale = 0.08838834764831845f;
    const float* Qg = g_q + (size_t)bh * Ss * Dh;
    const float* Kg = g_k + (size_t)bh * Ss * Dh;

    for (int t = 0; t < NT; ++t) {
        const int r = t * 128 + 127;
        if (tid < 32)
            *(float4*)&qrow[tid * 4] = *(const float4*)(Qg + (size_t)r * Dh + tid * 4);
        __syncthreads();

        float lv[8];
#pragma unroll
        for (int kk = 0; kk < 8; ++kk) {
            int k = tid * 8 + kk;
            float acc = 0.f;
            const float4* kr = (const float4*)(Kg + (size_t)k * Dh);
#pragma unroll
            for (int d4 = 0; d4 < 32; ++d4) {
                float4 kv = kr[d4];
                float4 qv = *(const float4*)&qrow[d4 * 4];
                acc += kv.x * qv.x + kv.y * qv.y + kv.z * qv.z + kv.w * qv.w;
            }
            lv[kk] = (k <= r) ? acc * scale : NEGV;
        }

        // row max
        float tm = lv[0];
#pragma unroll
        for (int kk = 1; kk < 8; ++kk) tm = fmaxf(tm, lv[kk]);
        red[tid] = tm;
        __syncthreads();
        for (int sft = 128; sft; sft >>= 1) {
            if (tid < sft) red[tid] = fmaxf(red[tid], red[tid + sft]);
            __syncthreads();
        }
        float mx = red[0];
        __syncthreads();

        // exp weights; per-thread tile-local max (each thread's 8 keys lie in one tile)
        float tmloc = 0.f;
#pragma unroll
        for (int kk = 0; kk < 8; ++kk) {
            float e = __expf(lv[kk] - mx);
            tmloc = fmaxf(tmloc, e);
        }
        red[tid] = tmloc;
        __syncthreads();
        if (tid < NT) {
            float v = red[tid * 16];
#pragma unroll
            for (int u = 1; u < 16; u++) v = fmaxf(v, red[tid * 16 + u]);
            ts[tid] = v;
        }
        __syncthreads();

        if (tid == 0) {
            float sc[NT];
#pragma unroll
            for (int u = 0; u < NT; u++) sc[u] = ts[u];
            int base = (bh * NT + t) * TOPK;
            for (int j = 0; j < TOPK; j++) {
                int best = 0; float bv = sc[0];
                for (int u = 1; u < NT; u++)
                    if (sc[u] > bv) { bv = sc[u]; best = u; }
                out_idx[base + j] = (float)best;
                sc[best] = -1.0f;
            }
        }
        __syncthreads();
    }
}

// ---------------------------------------------------------------------------
extern "C" void kernel_launch(void* const* d_in, const int* in_sizes, int n_in,
                              void* d_out, int out_size)
{
    const float* x    = (const float*)d_in[0];
    const float* wq   = (const float*)d_in[1];
    const float* wk   = (const float*)d_in[2];
    const float* wv   = (const float*)d_in[3];
    const float* wo   = (const float*)d_in[4];
    const float* cosr = (const float*)d_in[5];
    const float* sinr = (const float*)d_in[6];
    float* out = (float*)d_out;

    const int smem_flash = (3 * 128 * 132 + 16 * 128) * 4;   // 210944 B
    cudaFuncSetAttribute(flash_kernel,
                         cudaFuncAttributeMaxDynamicSharedMemorySize, smem_flash);

    qkv_gemm<<<dim3(32, 48), 256>>>(x, wq, wk, wv);

    const int nrope = Bb * Hh * Ss * 64;
    rope_kernel<<<(nrope + 255) / 256, 256>>>(cosr, sinr);

    const int n_main = Bb * Ss * Dm;                  // 8388608
    const int n_idx = Bb * Hh * NT * TOPK;            // 4096
    if (out_size >= n_main + n_idx) {
        // only needs q/k post-RoPE; 32 blocks — overlaps with flash below
        score_kernel<<<Bb * Hh, 256>>>(out + n_main);
    }

    flash_kernel<<<dim3(Bb * Hh, Ss / 128), 256, smem_flash>>>();

    oproj_gemm<<<dim3(32, 16), 256>>>(wo, out);
}

// round 13
// speedup vs baseline: 1.3244x; 1.3244x over previous
#include <cuda_runtime.h>
#include <cuda_bf16.h>
#include <mma.h>
#include <cstdint>

using namespace nvcuda;

#define NEGV (-1e10f)

constexpr int Bb = 2;
constexpr int Hh = 16;
constexpr int Ss = 2048;
constexpr int Dh = 128;
constexpr int Dm = 2048;     // Hh*Dh
constexpr int NT = 16;       // Ss / 128 tiles
constexpr int TOPK = 8;

// fp32 scratch
__device__ float g_q[Bb * Hh * Ss * Dh];    // [b,h,s,d]
__device__ float g_k[Bb * Hh * Ss * Dh];
__device__ float g_v[Bb * Hh * Ss * Dh];
__device__ float g_ao[Bb * Ss * Dm];        // attention out, [b,s,h*d]

// bf16-split scratch
__device__ __nv_bfloat16 g_xh[Bb * Ss * Dm];     // x hi
__device__ __nv_bfloat16 g_xl[Bb * Ss * Dm];     // x lo
__device__ __nv_bfloat16 g_aoh[Bb * Ss * Dm];    // ao hi
__device__ __nv_bfloat16 g_aol[Bb * Ss * Dm];    // ao lo
__device__ __nv_bfloat16 g_wth[4 * Dm * Dm];     // transposed weights hi  [w][n][k]
__device__ __nv_bfloat16 g_wtl[4 * Dm * Dm];     // transposed weights lo

// ---------------------------------------------------------------------------
// Split kernels: fp32 -> bf16 hi + bf16 lo
// ---------------------------------------------------------------------------
__global__ void split_x_kernel(const float* __restrict__ x) {
    int i = blockIdx.x * 1024 + threadIdx.x;
    float v = x[i];
    __nv_bfloat16 hi = __float2bfloat16(v);
    g_xh[i] = hi;
    g_xl[i] = __float2bfloat16(v - __bfloat162float(hi));
}

__global__ void split_ao_kernel() {
    int i = blockIdx.x * 1024 + threadIdx.x;
    float v = g_ao[i];
    __nv_bfloat16 hi = __float2bfloat16(v);
    g_aoh[i] = hi;
    g_aol[i] = __float2bfloat16(v - __bfloat162float(hi));
}

// Transpose + split 4 weight matrices: W[k][n] -> WT[n][k] hi/lo
__global__ __launch_bounds__(256) void wsplit_t_kernel(
    const float* __restrict__ wq, const float* __restrict__ wk,
    const float* __restrict__ wv, const float* __restrict__ wo)
{
    __shared__ float t[32][33];
    const int w = blockIdx.z;
    const float* W = (w == 0) ? wq : (w == 1) ? wk : (w == 2) ? wv : wo;
    const int n0 = blockIdx.x * 32, k0 = blockIdx.y * 32;
    const int tx = threadIdx.x & 31, ty = threadIdx.x >> 5;
#pragma unroll
    for (int i = 0; i < 4; ++i)
        t[ty + i * 8][tx] = W[(size_t)(k0 + ty + i * 8) * 2048 + n0 + tx];
    __syncthreads();
#pragma unroll
    for (int i = 0; i < 4; ++i) {
        float v = t[tx][ty + i * 8];
        __nv_bfloat16 hi = __float2bfloat16(v);
        size_t o = (size_t)w * 4194304 + (size_t)(n0 + ty + i * 8) * 2048 + k0 + tx;
        g_wth[o] = hi;
        g_wtl[o] = __float2bfloat16(v - __bfloat162float(hi));
    }
}

// ---------------------------------------------------------------------------
// WMMA (HMMA) bf16-split GEMM core: C[128x128] = A[128x2048] @ B^T.
// A/B given as bf16 hi/lo K-major arrays. 8 warps, warp tile 32x64, K-chunk 32.
// Double-buffered SMEM with register prefetch. Result left in Cs (float,
// stride 132) overlaying the same dynamic SMEM.
// SMEM: 2 stages x 4 matrices x [128][AST] bf16.
// ---------------------------------------------------------------------------
constexpr int AST = 40;                        // padded bf16 row stride
constexpr int MAT_ELE = 128 * AST;             // 5120 bf16 per matrix
constexpr int STAGE_ELE = 4 * MAT_ELE;         // 20480 bf16 per stage
constexpr int GEMM_SMEM = 2 * STAGE_ELE * 2;   // 81920 bytes (> Cs 67584)

__device__ void gemm_wmma_core(
    const __nv_bfloat16* __restrict__ pAh, const __nv_bfloat16* __restrict__ pAl,
    const __nv_bfloat16* __restrict__ pBh, const __nv_bfloat16* __restrict__ pBl,
    char* smx)
{
    __nv_bfloat16* sm = (__nv_bfloat16*)smx;
    const int tid = threadIdx.x;
    const int wid = tid >> 5;
    const int wm = wid >> 1;     // 0..3  (32-row band)
    const int wn = wid & 1;      // 0..1  (64-col band)

    wmma::fragment<wmma::accumulator, 16, 16, 16, float> c[2][4];
#pragma unroll
    for (int i = 0; i < 2; ++i)
#pragma unroll
        for (int j = 0; j < 4; ++j) wmma::fill_fragment(c[i][j], 0.0f);

    // per-thread load coordinates: 512 float4 per matrix-chunk / 256 threads = 2
    int grow[2], sofs[2];
#pragma unroll
    for (int i = 0; i < 2; ++i) {
        int idx = tid + (i << 8);          // 0..511
        int row = idx >> 2;                // 0..127
        int c8 = (idx & 3) << 3;           // 0,8,16,24
        grow[i] = row * 2048 + c8;
        sofs[i] = row * AST + c8;
    }

    // prologue: chunk 0 -> stage 0
#pragma unroll
    for (int i = 0; i < 2; ++i) {
        size_t g = (size_t)grow[i];
        *(float4*)(sm + sofs[i])               = *(const float4*)(pAh + g);
        *(float4*)(sm + MAT_ELE + sofs[i])     = *(const float4*)(pAl + g);
        *(float4*)(sm + 2 * MAT_ELE + sofs[i]) = *(const float4*)(pBh + g);
        *(float4*)(sm + 3 * MAT_ELE + sofs[i]) = *(const float4*)(pBl + g);
    }
    __syncthreads();

    for (int ch = 0; ch < 64; ++ch) {
        const int s = ch & 1;
        const __nv_bfloat16* st = sm + s * STAGE_ELE;
        const bool more = (ch < 63);

        // prefetch next chunk into registers (gmem only; overlaps compute)
        float4 vAh[2], vAl[2], vBh[2], vBl[2];
        if (more) {
            const int k0 = (ch + 1) << 5;
#pragma unroll
            for (int i = 0; i < 2; ++i) {
                size_t g = (size_t)grow[i] + k0;
                vAh[i] = *(const float4*)(pAh + g);
                vAl[i] = *(const float4*)(pAl + g);
                vBh[i] = *(const float4*)(pBh + g);
                vBl[i] = *(const float4*)(pBl + g);
            }
        }

        const __nv_bfloat16* Ah = st;
        const __nv_bfloat16* Al = st + MAT_ELE;
        const __nv_bfloat16* Bh = st + 2 * MAT_ELE;
        const __nv_bfloat16* Bl = st + 3 * MAT_ELE;

#pragma unroll
        for (int ks = 0; ks < 2; ++ks) {
            wmma::fragment<wmma::matrix_a, 16, 16, 16, __nv_bfloat16, wmma::row_major> ah[2], al[2];
            wmma::fragment<wmma::matrix_b, 16, 16, 16, __nv_bfloat16, wmma::col_major> bh[4], bl[4];
#pragma unroll
            for (int i = 0; i < 2; ++i) {
                const int r0 = wm * 32 + i * 16;
                wmma::load_matrix_sync(ah[i], Ah + r0 * AST + ks * 16, AST);
                wmma::load_matrix_sync(al[i], Al + r0 * AST + ks * 16, AST);
            }
#pragma unroll
            for (int j = 0; j < 4; ++j) {
                const int n0 = wn * 64 + j * 16;
                wmma::load_matrix_sync(bh[j], Bh + n0 * AST + ks * 16, AST);
                wmma::load_matrix_sync(bl[j], Bl + n0 * AST + ks * 16, AST);
            }
#pragma unroll
            for (int i = 0; i < 2; ++i)
#pragma unroll
                for (int j = 0; j < 4; ++j) {
                    wmma::mma_sync(c[i][j], ah[i], bh[j], c[i][j]);
                    wmma::mma_sync(c[i][j], ah[i], bl[j], c[i][j]);
                    wmma::mma_sync(c[i][j], al[i], bh[j], c[i][j]);
                    wmma::mma_sync(c[i][j], al[i], bl[j], c[i][j]);
                }
        }

        if (more) {
            __nv_bfloat16* nx = sm + (s ^ 1) * STAGE_ELE;
#pragma unroll
            for (int i = 0; i < 2; ++i) {
                *(float4*)(nx + sofs[i])               = vAh[i];
                *(float4*)(nx + MAT_ELE + sofs[i])     = vAl[i];
                *(float4*)(nx + 2 * MAT_ELE + sofs[i]) = vBh[i];
                *(float4*)(nx + 3 * MAT_ELE + sofs[i]) = vBl[i];
            }
        }
        __syncthreads();
    }

    // stage result to SMEM (float overlay; all compute is past the last sync)
    float* Cs = (float*)smx;
#pragma unroll
    for (int i = 0; i < 2; ++i)
#pragma unroll
        for (int j = 0; j < 4; ++j)
            wmma::store_matrix_sync(Cs + (wm * 32 + i * 16) * 132 + wn * 64 + j * 16,
                                    c[i][j], 132, wmma::mem_row_major);
    __syncthreads();
}

// ---------------------------------------------------------------------------
// QKV projection. grid=(32,48): y>>4 selects weight, y&15 selects head tile.
// Epilogue scatters fp32 into g_q/g_k/g_v [b,h,s,d].
// ---------------------------------------------------------------------------
__global__ __launch_bounds__(256, 1) void qkv_gemm_tc()
{
    extern __shared__ char smx[];
    const int which = blockIdx.y >> 4;
    const int h = blockIdx.y & 15;
    const int m0 = blockIdx.x * 128;
    const int n0 = h * 128;

    gemm_wmma_core(g_xh + (size_t)m0 * 2048,
                   g_xl + (size_t)m0 * 2048,
                   g_wth + ((size_t)which * 2048 + n0) * 2048,
                   g_wtl + ((size_t)which * 2048 + n0) * 2048, smx);

    const float* Cs = (const float*)smx;
    float* dst = (which == 0) ? g_q : (which == 1) ? g_k : g_v;
    const int tid = threadIdx.x;
#pragma unroll
    for (int it = 0; it < 16; ++it) {
        int idx = it * 256 + tid;
        int row = idx >> 5;
        int c4 = (idx & 31) << 2;
        float4 v = *(const float4*)&Cs[row * 132 + c4];
        int m = m0 + row;
        int b = m >> 11, sI = m & 2047;
        *(float4*)(dst + (((size_t)(b * Hh + h) * Ss + sI) * Dh) + c4) = v;
    }
}

// ---------------------------------------------------------------------------
// Output projection: out = g_ao @ wo. grid=(32,16).
// ---------------------------------------------------------------------------
__global__ __launch_bounds__(256, 1) void oproj_gemm_tc(float* __restrict__ out)
{
    extern __shared__ char smx[];
    const int m0 = blockIdx.x * 128;
    const int n0 = blockIdx.y * 128;

    gemm_wmma_core(g_aoh + (size_t)m0 * 2048,
                   g_aol + (size_t)m0 * 2048,
                   g_wth + ((size_t)3 * 2048 + n0) * 2048,
                   g_wtl + ((size_t)3 * 2048 + n0) * 2048, smx);

    const float* Cs = (const float*)smx;
    const int tid = threadIdx.x;
#pragma unroll
    for (int it = 0; it < 16; ++it) {
        int idx = it * 256 + tid;
        int row = idx >> 5;
        int c4 = (idx & 31) << 2;
        float4 v = *(const float4*)&Cs[row * 132 + c4];
        *(float4*)(out + (size_t)(m0 + row) * 2048 + n0 + c4) = v;
    }
}

// ---------------------------------------------------------------------------
// RoPE (rotate_half form), in-place on g_q and g_k.
// ---------------------------------------------------------------------------
__global__ void rope_kernel(const float* __restrict__ cosr,
                            const float* __restrict__ sinr)
{
    int idx = blockIdx.x * 256 + threadIdx.x;
    if (idx >= Bb * Hh * Ss * 64) return;
    int d = idx & 63;
    int s = (idx >> 6) & (Ss - 1);
    int bh = idx >> 17;
    float c = cosr[s * 64 + d];
    float sn = sinr[s * 64 + d];
    size_t base = (size_t)bh * Ss * Dh + (size_t)s * Dh;
    float q0 = g_q[base + d], q1 = g_q[base + d + 64];
    g_q[base + d] = q0 * c - q1 * sn;
    g_q[base + d + 64] = q1 * c + q0 * sn;
    float k0 = g_k[base + d], k1 = g_k[base + d + 64];
    g_k[base + d] = k0 * c - k1 * sn;
    g_k[base + d + 64] = k1 * c + k0 * sn;
}

// ---------------------------------------------------------------------------
// Flash-style causal attention (fp32 SIMT). grid = (B*H, S/128). 256 threads.
// Heavy-first schedule: qt = NT-1-blockIdx.y (LPT balance).
// ---------------------------------------------------------------------------
__global__ __launch_bounds__(256, 1) void flash_kernel()
{
    extern __shared__ float sm[];
    float* Qt = sm;                       // [128 d][132]
    float* Kt = sm + 128 * 132;           // [128 d][132]
    float* Ps = sm + 2 * 128 * 132;       // [128 row][132]
    float* Vs = sm + 3 * 128 * 132;       // [16 kk][128 d]

    const int bh = blockIdx.x;
    const int qt = (NT - 1) - blockIdx.y;      // heavy tiles first
    const int tid = threadIdx.x;
    const int ty = tid >> 4, tx = tid & 15;
    const float scale = 0.08838834764831845f;   // 1/sqrt(128)

    const float* Qg = g_q + ((size_t)bh * Ss + (size_t)qt * 128) * Dh;
    const float* Kg = g_k + (size_t)bh * Ss * Dh;
    const float* Vg = g_v + (size_t)bh * Ss * Dh;

#pragma unroll
    for (int it = 0; it < 16; ++it) {
        int idx = it * 256 + tid;
        int row = idx >> 5;
        int c4 = (idx & 31) << 2;
        float4 v = *(const float4*)(Qg + (size_t)row * Dh + c4);
        Qt[(c4 + 0) * 132 + row] = v.x;
        Qt[(c4 + 1) * 132 + row] = v.y;
        Qt[(c4 + 2) * 132 + row] = v.z;
        Qt[(c4 + 3) * 132 + row] = v.w;
    }

    float o[8][8];
    float mrow[8], lrow[8];
#pragma unroll
    for (int i = 0; i < 8; i++) {
        mrow[i] = -1e30f; lrow[i] = 0.f;
#pragma unroll
        for (int j = 0; j < 8; j++) o[i][j] = 0.f;
    }
    __syncthreads();

    for (int kt = 0; kt <= qt; ++kt) {
#pragma unroll
        for (int it = 0; it < 16; ++it) {
            int idx = it * 256 + tid;
            int row = idx >> 5;
            int c4 = (idx & 31) << 2;
            float4 v = *(const float4*)(Kg + (size_t)(kt * 128 + row) * Dh + c4);
            Kt[(c4 + 0) * 132 + row] = v.x;
            Kt[(c4 + 1) * 132 + row] = v.y;
            Kt[(c4 + 2) * 132 + row] = v.z;
            Kt[(c4 + 3) * 132 + row] = v.w;
        }
        __syncthreads();

        float sacc[8][8];
#pragma unroll
        for (int i = 0; i < 8; i++)
#pragma unroll
            for (int j = 0; j < 8; j++) sacc[i][j] = 0.f;

#pragma unroll 4
        for (int d = 0; d < Dh; ++d) {
            float a[8], b[8];
            *(float4*)&a[0] = *(const float4*)&Qt[d * 132 + ty * 8];
            *(float4*)&a[4] = *(const float4*)&Qt[d * 132 + ty * 8 + 4];
            *(float4*)&b[0] = *(const float4*)&Kt[d * 132 + tx * 8];
            *(float4*)&b[4] = *(const float4*)&Kt[d * 132 + tx * 8 + 4];
#pragma unroll
            for (int i = 0; i < 8; i++)
#pragma unroll
                for (int j = 0; j < 8; j++) sacc[i][j] += a[i] * b[j];
        }

        const bool diag = (kt == qt);
        const int rb = ty * 8, cb = tx * 8;
#pragma unroll
        for (int i = 0; i < 8; i++)
#pragma unroll
            for (int j = 0; j < 8; j++) {
                float v = sacc[i][j] * scale;
                if (diag && (cb + j > rb + i)) v = NEGV;
                sacc[i][j] = v;
            }

#pragma unroll
        for (int i = 0; i < 8; i++) {
            float tm = sacc[i][0];
#pragma unroll
            for (int j = 1; j < 8; j++) tm = fmaxf(tm, sacc[i][j]);
#pragma unroll
            for (int off = 8; off; off >>= 1)
                tm = fmaxf(tm, __shfl_xor_sync(0xffffffffu, tm, off));
            float mn = fmaxf(mrow[i], tm);
            float al = __expf(mrow[i] - mn);
            mrow[i] = mn;
            float rs = 0.f;
#pragma unroll
            for (int j = 0; j < 8; j++) {
                float p = __expf(sacc[i][j] - mn);
                sacc[i][j] = p;
                rs += p;
            }
#pragma unroll
            for (int off = 8; off; off >>= 1)
                rs += __shfl_xor_sync(0xffffffffu, rs, off);
            lrow[i] = lrow[i] * al + rs;
#pragma unroll
            for (int j = 0; j < 8; j++) o[i][j] *= al;
        }

#pragma unroll
        for (int i = 0; i < 8; i++) {
            float* pp = &Ps[(ty * 8 + i) * 132 + tx * 8];
            *(float4*)pp = make_float4(sacc[i][0], sacc[i][1], sacc[i][2], sacc[i][3]);
            *(float4*)(pp + 4) = make_float4(sacc[i][4], sacc[i][5], sacc[i][6], sacc[i][7]);
        }
        __syncthreads();

        const float* Vt = Vg + (size_t)kt * 128 * Dh;
        for (int kk0 = 0; kk0 < 128; kk0 += 16) {
#pragma unroll
            for (int it = 0; it < 2; ++it) {
                int idx = it * 256 + tid;
                int r = idx >> 5;
                int c4 = (idx & 31) << 2;
                *(float4*)&Vs[r * 128 + c4] =
                    *(const float4*)(Vt + (size_t)(kk0 + r) * Dh + c4);
            }
            __syncthreads();
#pragma unroll
            for (int kq = 0; kq < 4; ++kq) {
                float4 p4[8];
#pragma unroll
                for (int i = 0; i < 8; i++)
                    p4[i] = *(const float4*)&Ps[(ty * 8 + i) * 132 + kk0 + kq * 4];
#pragma unroll
                for (int c = 0; c < 4; c++) {
                    float b[8];
                    *(float4*)&b[0] = *(const float4*)&Vs[(kq * 4 + c) * 128 + tx * 8];
                    *(float4*)&b[4] = *(const float4*)&Vs[(kq * 4 + c) * 128 + tx * 8 + 4];
#pragma unroll
                    for (int i = 0; i < 8; i++) {
                        float pv = (&p4[i].x)[c];
#pragma unroll
                        for (int j = 0; j < 8; j++) o[i][j] += pv * b[j];
                    }
                }
            }
            __syncthreads();
        }
    }

    const int b = bh >> 4, h = bh & 15;
#pragma unroll
    for (int i = 0; i < 8; i++) {
        int s = qt * 128 + ty * 8 + i;
        float inv = 1.0f / lrow[i];
        float* p = g_ao + ((size_t)(b * Ss + s)) * Dm + h * 128 + tx * 8;
        *(float4*)p = make_float4(o[i][0] * inv, o[i][1] * inv, o[i][2] * inv, o[i][3] * inv);
        *(float4*)(p + 4) = make_float4(o[i][4] * inv, o[i][5] * inv, o[i][6] * inv, o[i][7] * inv);
    }
}

// ---------------------------------------------------------------------------
// Tile scoring + top-k (unchanged from passing version).
// ---------------------------------------------------------------------------
__global__ __launch_bounds__(256) void score_kernel(float* __restrict__ out_idx)
{
    __shared__ float qrow[128];
    __shared__ float red[256];
    __shared__ float ts[NT];

    const int bh = blockIdx.x;
    const int tid = threadIdx.x;
    const float scale = 0.08838834764831845f;
    const float* Qg = g_q + (size_t)bh * Ss * Dh;
    const float* Kg = g_k + (size_t)bh * Ss * Dh;

    for (int t = 0; t < NT; ++t) {
        const int r = t * 128 + 127;
        if (tid < 32)
            *(float4*)&qrow[tid * 4] = *(const float4*)(Qg + (size_t)r * Dh + tid * 4);
        __syncthreads();

        float lv[8];
#pragma unroll
        for (int kk = 0; kk < 8; ++kk) {
            int k = tid * 8 + kk;
            float acc = 0.f;
            const float4* kr = (const float4*)(Kg + (size_t)k * Dh);
#pragma unroll
            for (int d4 = 0; d4 < 32; ++d4) {
                float4 kv = kr[d4];
                float4 qv = *(const float4*)&qrow[d4 * 4];
                acc += kv.x * qv.x + kv.y * qv.y + kv.z * qv.z + kv.w * qv.w;
            }
            lv[kk] = (k <= r) ? acc * scale : NEGV;
        }

        float tm = lv[0];
#pragma unroll
        for (int kk = 1; kk < 8; ++kk) tm = fmaxf(tm, lv[kk]);
        red[tid] = tm;
        __syncthreads();
        for (int sft = 128; sft; sft >>= 1) {
            if (tid < sft) red[tid] = fmaxf(red[tid], red[tid + sft]);
            __syncthreads();
        }
        float mx = red[0];
        __syncthreads();

        float tmloc = 0.f;
#pragma unroll
        for (int kk = 0; kk < 8; ++kk) {
            float e = __expf(lv[kk] - mx);
            tmloc = fmaxf(tmloc, e);
        }
        red[tid] = tmloc;
        __syncthreads();
        if (tid < NT) {
            float v = red[tid * 16];
#pragma unroll
            for (int u = 1; u < 16; u++) v = fmaxf(v, red[tid * 16 + u]);
            ts[tid] = v;
        }
        __syncthreads();

        if (tid == 0) {
            float sc[NT];
#pragma unroll
            for (int u = 0; u < NT; u++) sc[u] = ts[u];
            int base = (bh * NT + t) * TOPK;
            for (int j = 0; j < TOPK; j++) {
                int best = 0; float bv = sc[0];
                for (int u = 1; u < NT; u++)
                    if (sc[u] > bv) { bv = sc[u]; best = u; }
                out_idx[base + j] = (float)best;
                sc[best] = -1.0f;
            }
        }
        __syncthreads();
    }
}

// ---------------------------------------------------------------------------
extern "C" void kernel_launch(void* const* d_in, const int* in_sizes, int n_in,
                              void* d_out, int out_size)
{
    const float* x    = (const float*)d_in[0];
    const float* wq   = (const float*)d_in[1];
    const float* wk   = (const float*)d_in[2];
    const float* wv   = (const float*)d_in[3];
    const float* wo   = (const float*)d_in[4];
    const float* cosr = (const float*)d_in[5];
    const float* sinr = (const float*)d_in[6];
    float* out = (float*)d_out;

    const int smem_flash = (3 * 128 * 132 + 16 * 128) * 4;   // 210944 B
    cudaFuncSetAttribute(flash_kernel,
                         cudaFuncAttributeMaxDynamicSharedMemorySize, smem_flash);
    cudaFuncSetAttribute(qkv_gemm_tc,
                         cudaFuncAttributeMaxDynamicSharedMemorySize, GEMM_SMEM);
    cudaFuncSetAttribute(oproj_gemm_tc,
                         cudaFuncAttributeMaxDynamicSharedMemorySize, GEMM_SMEM);

    split_x_kernel<<<8192, 1024>>>(x);
    wsplit_t_kernel<<<dim3(64, 64, 4), 256>>>(wq, wk, wv, wo);

    qkv_gemm_tc<<<dim3(32, 48), 256, GEMM_SMEM>>>();

    const int nrope = Bb * Hh * Ss * 64;
    rope_kernel<<<(nrope + 255) / 256, 256>>>(cosr, sinr);

    const int n_main = Bb * Ss * Dm;                  // 8388608
    const int n_idx = Bb * Hh * NT * TOPK;            // 4096
    if (out_size >= n_main + n_idx) {
        score_kernel<<<Bb * Hh, 256>>>(out + n_main);
    }

    flash_kernel<<<dim3(Bb * Hh, Ss / 128), 256, smem_flash>>>();

    split_ao_kernel<<<8192, 1024>>>();
    oproj_gemm_tc<<<dim3(32, 16), 256, GEMM_SMEM>>>(out);
}